// round 2
// baseline (speedup 1.0000x reference)
#include <cuda_runtime.h>

// Problem constants (fixed shapes from setup_inputs)
#define B_   4
#define H_   480
#define W_   640
#define HW_  (H_ * W_)          // 307200
#define NPIX (B_ * HW_)         // 1228800
#define OFF_THRESH 0.5f

// One thread handles 4 consecutive pixels (aligned float4).
// Reads:  x,y,z,r (4 x float4) + key_query (9 x float4)
// Writes: 36 x float4 (9 window slots x 4 channels), plane-strided by HW_.
__global__ __launch_bounds__(256) void smap3x3_kernel(
    const float* __restrict__ x, const float* __restrict__ y,
    const float* __restrict__ z, const float* __restrict__ r,
    const float* __restrict__ kq, float* __restrict__ out)
{
    int t = blockIdx.x * blockDim.x + threadIdx.x;
    int g = t * 4;                       // global pixel index (first of 4)
    if (g >= NPIX) return;
    int b = g / HW_;
    int p = g - b * HW_;                 // within-batch pixel offset (HW_ % 4 == 0)

    // ---- load x,y,z,r ----
    float4 x4 = *(const float4*)(x + g);
    float4 y4 = *(const float4*)(y + g);
    float4 z4 = *(const float4*)(z + g);
    float4 r4 = *(const float4*)(r + g);
    float xv[4] = {x4.x, x4.y, x4.z, x4.w};
    float yv[4] = {y4.x, y4.y, y4.z, y4.w};
    float zv[4] = {z4.x, z4.y, z4.z, z4.w};
    float rv[4] = {r4.x, r4.y, r4.z, r4.w};

    // ---- argmin over 9 key_query planes (first-occurrence via strict <) ----
    const float* kqb = kq + (size_t)b * 9 * HW_ + p;
    float minv[4];
    int   mind[4];
    {
        float4 v = *(const float4*)(kqb);
        minv[0] = v.x; minv[1] = v.y; minv[2] = v.z; minv[3] = v.w;
        mind[0] = mind[1] = mind[2] = mind[3] = 0;
    }
    #pragma unroll
    for (int q = 1; q < 9; q++) {
        float4 v = *(const float4*)(kqb + q * HW_);
        float vv[4] = {v.x, v.y, v.z, v.w};
        #pragma unroll
        for (int l = 0; l < 4; l++) {
            if (vv[l] < minv[l]) { minv[l] = vv[l]; mind[l] = q; }
        }
    }

    // ---- selection indices per pixel ----
    // widx : window slot receiving (x,y,z); -1 => none (all-zero xz block)
    // w2idx: window slot receiving r; always valid
    int widx[4], w2idx[4];
    #pragma unroll
    for (int l = 0; l < 4; l++) {
        bool rm = rv[l] > OFF_THRESH;
        bool zp = zv[l] > 0.0f;
        widx[l]  = rm ? (zp ? mind[l] : 4) : -1;
        w2idx[l] = (rm && zp) ? mind[l] : 4;
    }

    // ---- emit 9 window slots x 4 channels ----
    float* ob = out + (size_t)b * 36 * HW_ + p;
    #pragma unroll
    for (int st = 0; st < 9; st++) {
        float ox[4], oy[4], oz[4], orr[4];
        #pragma unroll
        for (int l = 0; l < 4; l++) {
            bool s  = (widx[l]  == st);
            bool s2 = (w2idx[l] == st);
            ox[l]  = s  ? xv[l] : 0.0f;
            oy[l]  = s  ? yv[l] : 0.0f;
            oz[l]  = s  ? zv[l] : 0.0f;
            orr[l] = s2 ? rv[l] : 0.0f;
        }
        float* pb = ob + (size_t)(st * 4) * HW_;
        *(float4*)(pb + 0 * HW_) = make_float4(ox[0], ox[1], ox[2], ox[3]);
        *(float4*)(pb + 1 * HW_) = make_float4(oy[0], oy[1], oy[2], oy[3]);
        *(float4*)(pb + 2 * HW_) = make_float4(oz[0], oz[1], oz[2], oz[3]);
        *(float4*)(pb + 3 * HW_) = make_float4(orr[0], orr[1], orr[2], orr[3]);
    }
}

extern "C" void kernel_launch(void* const* d_in, const int* in_sizes, int n_in,
                              void* d_out, int out_size)
{
    const float* x  = (const float*)d_in[0];
    const float* y  = (const float*)d_in[1];
    const float* z  = (const float*)d_in[2];
    const float* r  = (const float*)d_in[3];
    const float* kq = (const float*)d_in[4];
    float* out = (float*)d_out;

    const int threads = 256;
    const int nthreads_total = NPIX / 4;            // 307200
    const int blocks = (nthreads_total + threads - 1) / threads;  // 1200
    smap3x3_kernel<<<blocks, threads>>>(x, y, z, r, kq, out);
}

// round 3
// speedup vs baseline: 1.0103x; 1.0103x over previous
#include <cuda_runtime.h>

// Problem constants (fixed shapes from setup_inputs)
#define B_   4
#define H_   480
#define W_   640
#define HW_  (H_ * W_)          // 307200
#define NPIX (B_ * HW_)         // 1228800
#define OFF_THRESH 0.5f

// One thread handles 4 consecutive pixels (aligned float4).
// Reads:  x,y,z,r (4 x float4) + key_query (9 x float4)  -- all streaming (.cs)
// Writes: 36 x float4 (9 window slots x 4 channels), plane-strided, streaming (.cs)
__global__ __launch_bounds__(128) void smap3x3_kernel(
    const float* __restrict__ x, const float* __restrict__ y,
    const float* __restrict__ z, const float* __restrict__ r,
    const float* __restrict__ kq, float* __restrict__ out)
{
    int t = blockIdx.x * blockDim.x + threadIdx.x;
    int g = t * 4;                       // global pixel index (first of 4)
    if (g >= NPIX) return;
    int b = g / HW_;
    int p = g - b * HW_;                 // within-batch pixel offset (HW_ % 4 == 0)

    // ---- load x,y,z,r (streaming) ----
    float4 x4 = __ldcs((const float4*)(x + g));
    float4 y4 = __ldcs((const float4*)(y + g));
    float4 z4 = __ldcs((const float4*)(z + g));
    float4 r4 = __ldcs((const float4*)(r + g));
    float xv[4] = {x4.x, x4.y, x4.z, x4.w};
    float yv[4] = {y4.x, y4.y, y4.z, y4.w};
    float zv[4] = {z4.x, z4.y, z4.z, z4.w};
    float rv[4] = {r4.x, r4.y, r4.z, r4.w};

    // ---- argmin over 9 key_query planes (first-occurrence via strict <) ----
    const float* kqb = kq + (size_t)b * 9 * HW_ + p;
    float minv[4];
    int   mind[4];
    {
        float4 v = __ldcs((const float4*)(kqb));
        minv[0] = v.x; minv[1] = v.y; minv[2] = v.z; minv[3] = v.w;
        mind[0] = mind[1] = mind[2] = mind[3] = 0;
    }
    #pragma unroll
    for (int q = 1; q < 9; q++) {
        float4 v = __ldcs((const float4*)(kqb + q * HW_));
        float vv[4] = {v.x, v.y, v.z, v.w};
        #pragma unroll
        for (int l = 0; l < 4; l++) {
            if (vv[l] < minv[l]) { minv[l] = vv[l]; mind[l] = q; }
        }
    }

    // ---- selection indices per pixel ----
    // widx : window slot receiving (x,y,z); -1 => none (all-zero xz block)
    // w2idx: window slot receiving r; always valid
    int widx[4], w2idx[4];
    #pragma unroll
    for (int l = 0; l < 4; l++) {
        bool rm = rv[l] > OFF_THRESH;
        bool zp = zv[l] > 0.0f;
        widx[l]  = rm ? (zp ? mind[l] : 4) : -1;
        w2idx[l] = (rm && zp) ? mind[l] : 4;
    }

    // ---- emit 9 window slots x 4 channels (streaming stores) ----
    float* ob = out + (size_t)b * 36 * HW_ + p;
    #pragma unroll
    for (int st = 0; st < 9; st++) {
        float ox[4], oy[4], oz[4], orr[4];
        #pragma unroll
        for (int l = 0; l < 4; l++) {
            bool s  = (widx[l]  == st);
            bool s2 = (w2idx[l] == st);
            ox[l]  = s  ? xv[l] : 0.0f;
            oy[l]  = s  ? yv[l] : 0.0f;
            oz[l]  = s  ? zv[l] : 0.0f;
            orr[l] = s2 ? rv[l] : 0.0f;
        }
        float* pb = ob + (size_t)(st * 4) * HW_;
        __stcs((float4*)(pb + 0 * HW_), make_float4(ox[0], ox[1], ox[2], ox[3]));
        __stcs((float4*)(pb + 1 * HW_), make_float4(oy[0], oy[1], oy[2], oy[3]));
        __stcs((float4*)(pb + 2 * HW_), make_float4(oz[0], oz[1], oz[2], oz[3]));
        __stcs((float4*)(pb + 3 * HW_), make_float4(orr[0], orr[1], orr[2], orr[3]));
    }
}

extern "C" void kernel_launch(void* const* d_in, const int* in_sizes, int n_in,
                              void* d_out, int out_size)
{
    const float* x  = (const float*)d_in[0];
    const float* y  = (const float*)d_in[1];
    const float* z  = (const float*)d_in[2];
    const float* r  = (const float*)d_in[3];
    const float* kq = (const float*)d_in[4];
    float* out = (float*)d_out;

    const int threads = 128;
    const int nthreads_total = NPIX / 4;            // 307200
    const int blocks = (nthreads_total + threads - 1) / threads;  // 2400
    smap3x3_kernel<<<blocks, threads>>>(x, y, z, r, kq, out);
}